// round 5
// baseline (speedup 1.0000x reference)
#include <cuda_runtime.h>

#define NMOL 1024
#define MOLSIZE 128
#define MAXP 8128          // 128*127/2 upper-triangle max per molecule
#define GRID 512           // resident: 148 SMs x 4 blocks = 592 >= 512
#define MPB 2              // molecules per block

// ---- static device scratch (no runtime allocation allowed) ----
__device__ int            g_atomCnt[NMOL];
__device__ int            g_pairCnt[NMOL];
__device__ int            g_atomBase[NMOL];
__device__ int            g_pairBase[NMOL];
__device__ int            g_nReal;
__device__ int            g_nPairs;
__device__ int            g_ticket  = 0;
__device__ int            g_ticket2 = 0;
__device__ int            g_flag    = 0;
__device__ unsigned short g_pairList[NMOL * MAXP];   // (a<<8)|b row-major per molecule

// d2 threshold replicating (sqrtf(d2) < 5.0f): largest excluded d2 is 25-1ulp.
__device__ __forceinline__ float d2_thresh() { return __int_as_float(0x41C7FFFF); }

// bits strictly greater than a, restricted to 32-bit word w
__device__ __forceinline__ unsigned gt_mask(int a, int w) {
    const int aw = a >> 5;
    if (w < aw) return 0u;
    if (w > aw) return 0xffffffffu;
    return ~((2u << (a & 31)) - 1u);   // a&31==31 -> 2<<31 wraps to 0 -> mask 0 (correct)
}

// ============================================================================
// Single persistent kernel: phase 1 (stats + pair detection + ordered lists),
// grid-wide scan via ticket, spin barrier, phase 2 (scatter all outputs).
// ============================================================================
__global__ void __launch_bounds__(256, 4)
k_all(const int* __restrict__ species, const float* __restrict__ coords,
      const float* __restrict__ tore, float* __restrict__ out)
{
    __shared__ float4   sc[MPB][MOLSIZE];
    __shared__ short    ssp[MPB][MOLSIZE];
    __shared__ int      srank[MPB][MOLSIZE];
    __shared__ unsigned rmask[MOLSIZE][4];
    __shared__ unsigned nbw[4];
    __shared__ int      sWI[4][3];
    __shared__ float    sWF[4];
    __shared__ int      sWC[4];
    __shared__ int      sScanA[8], sScanB[8];
    __shared__ int      sLast;

    const int tid  = threadIdx.x;
    const int a    = tid & 127;
    const int half = tid >> 7;            // j-range split
    const int lane = tid & 31;
    const int wid  = tid >> 5;            // 0..7
    const int m0   = blockIdx.x * MPB;

    // ---------------- PHASE 1: per-molecule detection ----------------
    #pragma unroll
    for (int ml = 0; ml < MPB; ml++) {
        const int m = m0 + ml;

        int sp = 0;
        if (half == 0) {
            sp = species[m * MOLSIZE + a];
            const float* cp = coords + (size_t)(m * MOLSIZE + a) * 3;
            sc[ml][a]  = make_float4(cp[0], cp[1], cp[2], 0.0f);
            ssp[ml][a] = (short)sp;

            int   h1 = (sp > 1), h2 = (sp == 1), h3 = (sp > 0);
            float f1 = tore[sp];
            #pragma unroll
            for (int o = 16; o; o >>= 1) {
                h1 += __shfl_down_sync(0xffffffffu, h1, o);
                h2 += __shfl_down_sync(0xffffffffu, h2, o);
                h3 += __shfl_down_sync(0xffffffffu, h3, o);
                f1 += __shfl_down_sync(0xffffffffu, f1, o);
            }
            if (lane == 0) { sWI[wid][0] = h1; sWI[wid][1] = h2; sWI[wid][2] = h3; sWF[wid] = f1; }
            const unsigned bal = __ballot_sync(0xffffffffu, sp > 0);
            if (lane == 0) nbw[wid] = bal;
        }
        __syncthreads();

        if (tid == 0) {
            int H = 0, Y = 0, N = 0; float F = 0.0f;
            #pragma unroll
            for (int w = 0; w < 4; w++) { H += sWI[w][0]; Y += sWI[w][1]; N += sWI[w][2]; F += sWF[w]; }
            out[2 + m]          = (float)H;               // nHeavy
            out[2 + NMOL + m]   = (float)Y;               // nHydro
            out[2 + 2*NMOL + m] = (float)(int)(F * 0.5f); // nocc
            g_atomCnt[m] = N;
            if (m == 0) { out[0] = (float)NMOL; out[1] = (float)MOLSIZE; }
        }

        if (half == 0) {                  // local rank among nonblank atoms
            int wb = 0;
            #pragma unroll
            for (int w = 0; w < 4; w++) if (w < wid) wb += __popc(nbw[w]);
            srank[ml][a] = wb + __popc(nbw[wid] & ((1u << lane) - 1u));
        }

        // broadcast j-sweep: this thread tests atom a vs j in [half*64, half*64+64)
        {
            const float4 me = sc[ml][a];
            const float x = me.x, y = me.y, z = me.z;
            const int jb = half * 64;
            unsigned a0 = 0u, a1 = 0u;
            #pragma unroll 16
            for (int jj = 0; jj < 64; jj++) {
                const float4 pj = sc[ml][jb + jj];      // broadcast (same addr warp-wide)
                const float dx = pj.x - x, dy = pj.y - y, dz = pj.z - z;
                const float d2 = __fmaf_rn(dx, dx, __fmaf_rn(dy, dy, dz * dz));
                const unsigned hit = (d2 < d2_thresh()) ? 1u : 0u;
                if (jj < 32) a0 |= hit << jj; else a1 |= hit << (jj - 32);
            }
            rmask[a][half * 2 + 0] = a0;
            rmask[a][half * 2 + 1] = a1;
        }
        __syncthreads();

        // half 0: mask (j>a, nonblank), count, ordered scan, emit
        unsigned r[4]; int cnt = 0;
        if (half == 0) {
            const unsigned own = (nbw[a >> 5] >> (a & 31)) & 1u ? 0xffffffffu : 0u;
            #pragma unroll
            for (int w = 0; w < 4; w++) {
                r[w] = rmask[a][w] & gt_mask(a, w) & nbw[w] & own;
                cnt += __popc(r[w]);
            }
            int incl = cnt;
            #pragma unroll
            for (int o = 1; o < 32; o <<= 1) {
                int v = __shfl_up_sync(0xffffffffu, incl, o);
                if (lane >= o) incl += v;
            }
            if (lane == 31) sWC[wid] = incl;
            cnt = incl - cnt;             // now holds intra-warp exclusive prefix
        }
        __syncthreads();
        if (half == 0) {
            int wb = 0;
            #pragma unroll
            for (int w = 0; w < 4; w++) if (w < wid) wb += sWC[w];
            const int excl = wb + cnt;
            if (tid == 0) g_pairCnt[m] = sWC[0] + sWC[1] + sWC[2] + sWC[3];

            unsigned short* dst = g_pairList + m * MAXP + excl;
            int k = 0;
            #pragma unroll
            for (int w = 0; w < 4; w++) {
                unsigned mm = r[w];
                while (mm) {
                    int b = (w << 5) + __ffs((int)mm) - 1;
                    mm &= mm - 1u;
                    dst[k++] = (unsigned short)((a << 8) | b);
                }
            }
        }
        __syncthreads();                  // rmask/nbw reused next molecule
    }

    // ---------------- grid ticket + scan (last block) ----------------
    if (tid == 0) {
        __threadfence();
        const int old = atomicAdd(&g_ticket, 1);
        sLast = (old == (int)gridDim.x - 1);
    }
    __syncthreads();
    if (sLast) {
        __threadfence();
        const int b4 = tid * 4;
        int oA[4], oB[4], sA = 0, sB = 0;
        #pragma unroll
        for (int q = 0; q < 4; q++) {
            oA[q] = g_atomCnt[b4 + q]; sA += oA[q];
            oB[q] = g_pairCnt[b4 + q]; sB += oB[q];
        }
        int ia = sA, ib = sB;
        #pragma unroll
        for (int o = 1; o < 32; o <<= 1) {
            int va = __shfl_up_sync(0xffffffffu, ia, o);
            int vb = __shfl_up_sync(0xffffffffu, ib, o);
            if (lane >= o) { ia += va; ib += vb; }
        }
        if (lane == 31) { sScanA[wid] = ia; sScanB[wid] = ib; }
        __syncthreads();
        int bA = 0, bB = 0;
        #pragma unroll
        for (int w = 0; w < 8; w++) if (w < wid) { bA += sScanA[w]; bB += sScanB[w]; }
        int pA = bA + ia - sA, pB = bB + ib - sB;
        #pragma unroll
        for (int q = 0; q < 4; q++) {
            g_atomBase[b4 + q] = pA; pA += oA[q];
            g_pairBase[b4 + q] = pB; pB += oB[q];
        }
        if (tid == 255) { g_nReal = pA; g_nPairs = pB; }
        __syncthreads();
        __threadfence();
        if (tid == 0) *(volatile int*)&g_flag = 1;
    }

    // ---------------- spin barrier ----------------
    if (tid == 0) { while (*(volatile int*)&g_flag == 0) {} }
    __syncthreads();
    __threadfence();

    // ---------------- PHASE 2: scatter outputs ----------------
    const int nReal = g_nReal;
    const int nP    = g_nPairs;
    const int P0    = 3074 + 3 * nReal;

    {   // one thread per atom (256 threads = 2 molecules x 128 atoms)
        const int ml = half, mA = m0 + ml;
        const int sp = ssp[ml][a];
        const int rank = g_atomBase[mA] + srank[ml][a];
        srank[ml][a] = rank;
        if (sp > 0) {
            out[3074 + rank]             = (float)sp;                                           // Z
            out[3074 + nReal + rank]     = (float)(a * (MOLSIZE + 1) + mA * MOLSIZE * MOLSIZE); // maskd
            out[3074 + 2 * nReal + rank] = (float)mA;                                           // atom_molid
        }
    }
    __syncthreads();

    #pragma unroll
    for (int ml = 0; ml < MPB; ml++) {
        const int mol  = m0 + ml;
        const int base = g_pairBase[mol];
        const int cnt  = g_pairCnt[mol];
        const unsigned short* pl = g_pairList + mol * MAXP;
        const float molf  = (float)mol;
        const float mbase = (float)(mol * (MOLSIZE * MOLSIZE));

        for (int t = tid; t < cnt; t += 256) {
            const int ab = pl[t];
            const int a2 = ab >> 8, b2 = ab & 255;
            const float4 pa = sc[ml][a2], pb = sc[ml][b2];
            const float dx = pb.x - pa.x, dy = pb.y - pa.y, dz = pb.z - pa.z;
            const float d2   = dx * dx + dy * dy + dz * dz;
            const float inv  = rsqrtf(d2);
            const float dist = d2 * inv;
            const int q = base + t;
            out[P0 + q]            = mbase + (float)(a2 * MOLSIZE + b2); // mask
            out[P0 + nP + q]       = molf;                               // pair_molid
            out[P0 + 2 * nP + q]   = (float)ssp[ml][a2];                 // ni
            out[P0 + 3 * nP + q]   = (float)ssp[ml][b2];                 // nj
            out[P0 + 4 * nP + q]   = (float)srank[ml][a2];               // idxi
            out[P0 + 5 * nP + q]   = (float)srank[ml][b2];               // idxj
            out[P0 + 6 * nP + 3 * q + 0] = dx * inv;                     // xij
            out[P0 + 6 * nP + 3 * q + 1] = dy * inv;
            out[P0 + 6 * nP + 3 * q + 2] = dz * inv;
            out[P0 + 9 * nP + q]   = dist * 1.8897261258369282f;         // rij
        }
    }

    // ---------------- reset for next graph replay ----------------
    if (tid == 0) {
        __threadfence();
        const int old = atomicAdd(&g_ticket2, 1);
        if (old == (int)gridDim.x - 1) {    // everyone is past the spin
            g_ticket  = 0;
            g_ticket2 = 0;
            g_flag    = 0;
        }
    }
}

// ============================================================================
extern "C" void kernel_launch(void* const* d_in, const int* in_sizes, int n_in,
                              void* d_out, int out_size)
{
    const int*   species = (const int*)d_in[0];
    const float* coords  = (const float*)d_in[1];
    const float* tore    = (const float*)d_in[2];
    float*       out     = (float*)d_out;
    (void)in_sizes; (void)n_in; (void)out_size;

    k_all<<<GRID, 256>>>(species, coords, tore, out);
}

// round 6
// speedup vs baseline: 1.0816x; 1.0816x over previous
#include <cuda_runtime.h>

#define NMOL 1024
#define MOLSIZE 128
#define MAXP 8128          // 128*127/2 upper-triangle max per molecule

// ---- static device scratch (no runtime allocation allowed) ----
__device__ int            g_atomCnt[NMOL];
__device__ int            g_pairCnt[NMOL];
__device__ int            g_atomBase[NMOL];
__device__ int            g_pairBase[NMOL];
__device__ int            g_nReal;
__device__ int            g_nPairs;
__device__ int            g_ticket = 0;
__device__ int            g_atomInfo[NMOL * MOLSIZE];    // species | (localrank<<8)
__device__ unsigned short g_pairList[NMOL * MAXP];       // (a<<8)|b row-major per molecule

// d2 threshold replicating (sqrtf(d2) < 5.0f): largest excluded d2 is 25-1ulp.
__device__ __forceinline__ float d2_thresh() { return __int_as_float(0x41C7FFFF); }

// bits strictly greater than a, restricted to 32-bit word w
__device__ __forceinline__ unsigned gt_mask(int a, int w) {
    const int aw = a >> 5;
    if (w < aw) return 0u;
    if (w > aw) return 0xffffffffu;
    return ~((2u << (a & 31)) - 1u);   // a&31==31 -> mask 0 (correct)
}

// ============================================================================
// K1: one molecule per 256-thread block. Broadcast j-sweep (no atomics):
// thread (a, half) tests atom a against j in [half*64, half*64+64) reading
// sc[j] warp-uniform (conflict-free broadcast), accumulating a register
// bitmask. Ordering filters (j>a, nonblank) applied as post-masks so the
// emitted row-major order is bit-identical. Fused cross-molecule scan.
// ============================================================================
__global__ void __launch_bounds__(256)
k_count(const int* __restrict__ species, const float* __restrict__ coords,
        const float* __restrict__ tore, float* __restrict__ out)
{
    __shared__ float4   sc[MOLSIZE];
    __shared__ unsigned rmask[MOLSIZE][4];
    __shared__ unsigned nbw[4];
    __shared__ int      sWI[4][3];
    __shared__ float    sWF[4];
    __shared__ int      sWC[4];
    __shared__ int      sScanA[8], sScanB[8];
    __shared__ int      sLast;

    const int tid  = threadIdx.x;
    const int a    = tid & 127;
    const int half = tid >> 7;
    const int lane = tid & 31;
    const int wid  = tid >> 5;          // 0..7
    const int m    = blockIdx.x;

    if (half == 0) {
        const int sp = species[m * MOLSIZE + a];
        const float* cp = coords + (size_t)(m * MOLSIZE + a) * 3;
        sc[a] = make_float4(cp[0], cp[1], cp[2], 0.0f);

        const unsigned bH = __ballot_sync(0xffffffffu, sp > 1);
        const unsigned bY = __ballot_sync(0xffffffffu, sp == 1);
        const unsigned bN = __ballot_sync(0xffffffffu, sp > 0);
        float f1 = tore[sp];
        #pragma unroll
        for (int o = 16; o; o >>= 1) f1 += __shfl_down_sync(0xffffffffu, f1, o);
        if (lane == 0) {
            sWI[wid][0] = __popc(bH); sWI[wid][1] = __popc(bY); sWI[wid][2] = __popc(bN);
            sWF[wid] = f1; nbw[wid] = bN;
        }
        // stash sp for later (register, reused below via this branch only)
        // local rank needs nbw of lower warps -> after barrier
    }
    __syncthreads();

    if (tid == 0) {
        int H = 0, Y = 0, N = 0; float F = 0.0f;
        #pragma unroll
        for (int w = 0; w < 4; w++) { H += sWI[w][0]; Y += sWI[w][1]; N += sWI[w][2]; F += sWF[w]; }
        out[2 + m]          = (float)H;               // nHeavy
        out[2 + NMOL + m]   = (float)Y;               // nHydro
        out[2 + 2*NMOL + m] = (float)(int)(F * 0.5f); // nocc
        g_atomCnt[m] = N;
        if (m == 0) { out[0] = (float)NMOL; out[1] = (float)MOLSIZE; }
    }

    if (half == 0) {                   // local rank among nonblank atoms
        int wb = 0;
        #pragma unroll
        for (int w = 0; w < 4; w++) if (w < wid) wb += __popc(nbw[w]);
        const int lrank = wb + __popc(nbw[wid] & ((1u << lane) - 1u));
        const int sp = (int)((nbw[wid] >> lane) & 1u);  // placeholder to keep flow simple
        (void)sp;
        g_atomInfo[m * MOLSIZE + a] = species[m * MOLSIZE + a] | (lrank << 8);
    }

    // ---- broadcast j-sweep ----
    {
        const float4 me = sc[a];
        const float x = me.x, y = me.y, z = me.z;
        const int jb = half * 64;
        unsigned a0 = 0u, a1 = 0u;
        #pragma unroll 16
        for (int jj = 0; jj < 64; jj++) {
            const float4 pj = sc[jb + jj];             // warp-uniform address: broadcast
            const float dx = pj.x - x, dy = pj.y - y, dz = pj.z - z;
            const float d2 = __fmaf_rn(dx, dx, __fmaf_rn(dy, dy, dz * dz));
            const unsigned hit = (d2 < d2_thresh()) ? 1u : 0u;
            if (jj < 32) a0 |= hit << jj; else a1 |= hit << (jj - 32);
        }
        rmask[a][half * 2 + 0] = a0;
        rmask[a][half * 2 + 1] = a1;
    }
    __syncthreads();

    // ---- half 0: post-mask, count, ordered scan ----
    unsigned r[4]; int excl = 0;
    if (half == 0) {
        const unsigned own = (nbw[a >> 5] >> (a & 31)) & 1u ? 0xffffffffu : 0u;
        int cnt = 0;
        #pragma unroll
        for (int w = 0; w < 4; w++) {
            r[w] = rmask[a][w] & gt_mask(a, w) & nbw[w] & own;
            cnt += __popc(r[w]);
        }
        int incl = cnt;
        #pragma unroll
        for (int o = 1; o < 32; o <<= 1) {
            int v = __shfl_up_sync(0xffffffffu, incl, o);
            if (lane >= o) incl += v;
        }
        if (lane == 31) sWC[wid] = incl;
        excl = incl - cnt;
    }
    __syncthreads();
    if (half == 0) {
        int wb = 0;
        #pragma unroll
        for (int w = 0; w < 4; w++) if (w < wid) wb += sWC[w];
        excl += wb;
        if (tid == 0) g_pairCnt[m] = sWC[0] + sWC[1] + sWC[2] + sWC[3];

        unsigned short* dst = g_pairList + m * MAXP + excl;
        int k = 0;
        #pragma unroll
        for (int w = 0; w < 4; w++) {
            unsigned mm = r[w];
            while (mm) {
                int b = (w << 5) + __ffs((int)mm) - 1;
                mm &= mm - 1u;
                dst[k++] = (unsigned short)((a << 8) | b);
            }
        }
    }

    // ---- fused global scan: last block scans all 1024 counts ----
    __syncthreads();
    if (tid == 0) {
        __threadfence();
        int old = atomicAdd(&g_ticket, 1);
        sLast = (old == (int)gridDim.x - 1);
    }
    __syncthreads();
    if (sLast) {
        __threadfence();
        const int b4 = tid * 4;
        int oA[4], oB[4], sA = 0, sB = 0;
        #pragma unroll
        for (int q = 0; q < 4; q++) {
            oA[q] = g_atomCnt[b4 + q]; sA += oA[q];
            oB[q] = g_pairCnt[b4 + q]; sB += oB[q];
        }
        int ia = sA, ib = sB;
        #pragma unroll
        for (int o = 1; o < 32; o <<= 1) {
            int va = __shfl_up_sync(0xffffffffu, ia, o);
            int vb = __shfl_up_sync(0xffffffffu, ib, o);
            if (lane >= o) { ia += va; ib += vb; }
        }
        if (lane == 31) { sScanA[wid] = ia; sScanB[wid] = ib; }
        __syncthreads();
        int bA = 0, bB = 0;
        #pragma unroll
        for (int w = 0; w < 8; w++) if (w < wid) { bA += sScanA[w]; bB += sScanB[w]; }
        int pA = bA + ia - sA, pB = bB + ib - sB;
        #pragma unroll
        for (int q = 0; q < 4; q++) {
            g_atomBase[b4 + q] = pA; pA += oA[q];
            g_pairBase[b4 + q] = pB; pB += oB[q];
        }
        if (tid == 255) { g_nReal = pA; g_nPairs = pB; }
        if (tid == 0)   g_ticket = 0;    // reset for next graph replay
    }
}

// ============================================================================
// K2: scatter outputs; one molecule per 256-thread block (grid = 1024 for
// occupancy), rsqrt-based math, ranks via g_atomInfo.
// ============================================================================
__global__ void __launch_bounds__(256)
k_write(const float* __restrict__ coords, float* __restrict__ out)
{
    __shared__ float4 sc[MOLSIZE];
    __shared__ short  ssp[MOLSIZE];
    __shared__ int    srank[MOLSIZE];

    const int tid = threadIdx.x;
    const int m   = blockIdx.x;

    const int nReal = g_nReal;
    const int nP    = g_nPairs;
    const int P0    = 3074 + 3 * nReal;

    if (tid < MOLSIZE) {
        const int a     = tid;
        const int info  = g_atomInfo[m * MOLSIZE + a];
        const int sp    = info & 255;
        const int rank  = g_atomBase[m] + (info >> 8);
        const float* cp = coords + (size_t)(m * MOLSIZE + a) * 3;
        sc[a]    = make_float4(cp[0], cp[1], cp[2], 0.0f);
        ssp[a]   = (short)sp;
        srank[a] = rank;
        if (sp > 0) {
            out[3074 + rank]             = (float)sp;                                          // Z
            out[3074 + nReal + rank]     = (float)(a * (MOLSIZE + 1) + m * MOLSIZE * MOLSIZE); // maskd
            out[3074 + 2 * nReal + rank] = (float)m;                                           // atom_molid
        }
    }
    __syncthreads();

    const int base = g_pairBase[m];
    const int cnt  = g_pairCnt[m];
    const unsigned short* pl = g_pairList + m * MAXP;
    const float molf  = (float)m;
    const float mbase = (float)(m * (MOLSIZE * MOLSIZE));

    for (int t = tid; t < cnt; t += 256) {
        const int ab = pl[t];
        const int a2 = ab >> 8, b2 = ab & 255;
        const float4 pa = sc[a2], pb = sc[b2];
        const float dx = pb.x - pa.x, dy = pb.y - pa.y, dz = pb.z - pa.z;
        const float d2   = dx * dx + dy * dy + dz * dz;
        const float inv  = rsqrtf(d2);
        const float dist = d2 * inv;
        const int q = base + t;
        out[P0 + q]            = mbase + (float)(a2 * MOLSIZE + b2);  // mask
        out[P0 + nP + q]       = molf;                                // pair_molid
        out[P0 + 2 * nP + q]   = (float)ssp[a2];                      // ni
        out[P0 + 3 * nP + q]   = (float)ssp[b2];                      // nj
        out[P0 + 4 * nP + q]   = (float)srank[a2];                    // idxi
        out[P0 + 5 * nP + q]   = (float)srank[b2];                    // idxj
        out[P0 + 6 * nP + 3 * q + 0] = dx * inv;                      // xij
        out[P0 + 6 * nP + 3 * q + 1] = dy * inv;
        out[P0 + 6 * nP + 3 * q + 2] = dz * inv;
        out[P0 + 9 * nP + q]   = dist * 1.8897261258369282f;          // rij
    }
}

// ============================================================================
extern "C" void kernel_launch(void* const* d_in, const int* in_sizes, int n_in,
                              void* d_out, int out_size)
{
    const int*   species = (const int*)d_in[0];
    const float* coords  = (const float*)d_in[1];
    const float* tore    = (const float*)d_in[2];
    float*       out     = (float*)d_out;
    (void)in_sizes; (void)n_in; (void)out_size;

    k_count<<<NMOL, 256>>>(species, coords, tore, out);
    k_write<<<NMOL, 256>>>(coords, out);
}

// round 7
// speedup vs baseline: 1.4349x; 1.3266x over previous
#include <cuda_runtime.h>

#define NMOL 1024
#define MOLSIZE 128
#define MAXP 8128          // 128*127/2 upper-triangle max per molecule

// ---- static device scratch (no runtime allocation allowed) ----
__device__ int            g_atomCnt[NMOL];
__device__ int            g_pairCnt[NMOL];
__device__ int            g_atomBase[NMOL];
__device__ int            g_pairBase[NMOL];
__device__ int            g_nReal;
__device__ int            g_nPairs;
__device__ int            g_ticket = 0;
__device__ float4         g_pos4[NMOL * MOLSIZE];   // x,y,z, bits(sp | lrank<<8)
__device__ unsigned short g_pairList[NMOL * MAXP];  // (a<<8)|b row-major per molecule

// d2 threshold replicating (sqrtf(d2) < 5.0f): largest excluded d2 is 25-1ulp.
__device__ __forceinline__ float d2_thresh() { return __int_as_float(0x41C7FFFF); }

// bits strictly greater than a, restricted to 32-bit word w
__device__ __forceinline__ unsigned gt_mask(int a, int w) {
    const int aw = a >> 5;
    if (w < aw) return 0u;
    if (w > aw) return 0xffffffffu;
    return ~((2u << (a & 31)) - 1u);   // a&31==31 -> mask 0 (correct)
}

// ============================================================================
// K1: one molecule per 256-thread block. Triangle-only word-task sweep:
// 10 warp-tasks (row-group g, j-word w>=g). Within a task, lane handles row
// a=g*32+lane and sweeps the 32 j's of word w (j uniform across lanes ->
// conflict-free LDS broadcast). Each (a,w) mask word has exactly one writer:
// no atomics, no zeroing. Sub-diagonal words stay garbage and are ANDed away
// by gt_mask. Fused cross-molecule scan via ticket in the last block.
// ============================================================================
__global__ void __launch_bounds__(256)
k_count(const int* __restrict__ species, const float* __restrict__ coords,
        const float* __restrict__ tore, float* __restrict__ out)
{
    __shared__ float4   sc[MOLSIZE];
    __shared__ unsigned rmask[MOLSIZE][4];
    __shared__ unsigned nbw[4];
    __shared__ int      sWI[4][3];
    __shared__ float    sWF[4];
    __shared__ int      sWC[4];
    __shared__ int      sScanA[8], sScanB[8];
    __shared__ int      sLast;

    const int tid  = threadIdx.x;
    const int a    = tid & 127;
    const int lane = tid & 31;
    const int wid  = tid >> 5;          // 0..7
    const int m    = blockIdx.x;

    int   sp = 0;
    float x = 0.f, y = 0.f, z = 0.f;
    if (tid < 128) {
        sp = species[m * MOLSIZE + a];
        const float* cp = coords + (size_t)(m * MOLSIZE + a) * 3;
        x = cp[0]; y = cp[1]; z = cp[2];
        sc[a] = make_float4(x, y, z, 0.0f);

        const unsigned bH = __ballot_sync(0xffffffffu, sp > 1);
        const unsigned bY = __ballot_sync(0xffffffffu, sp == 1);
        const unsigned bN = __ballot_sync(0xffffffffu, sp > 0);
        float f1 = tore[sp];
        #pragma unroll
        for (int o = 16; o; o >>= 1) f1 += __shfl_down_sync(0xffffffffu, f1, o);
        if (lane == 0) {
            sWI[wid][0] = __popc(bH); sWI[wid][1] = __popc(bY); sWI[wid][2] = __popc(bN);
            sWF[wid] = f1; nbw[wid] = bN;
        }
    }
    __syncthreads();

    if (tid == 0) {
        int H = 0, Y = 0, N = 0; float F = 0.0f;
        #pragma unroll
        for (int w = 0; w < 4; w++) { H += sWI[w][0]; Y += sWI[w][1]; N += sWI[w][2]; F += sWF[w]; }
        out[2 + m]          = (float)H;               // nHeavy
        out[2 + NMOL + m]   = (float)Y;               // nHydro
        out[2 + 2*NMOL + m] = (float)(int)(F * 0.5f); // nocc
        g_atomCnt[m] = N;
        if (m == 0) { out[0] = (float)NMOL; out[1] = (float)MOLSIZE; }
    }

    if (tid < 128) {                    // pos4 handoff: coords + packed sp|lrank
        int wb = 0;
        #pragma unroll
        for (int w = 0; w < 4; w++) if (w < wid) wb += __popc(nbw[w]);
        const int lrank = wb + __popc(nbw[wid] & ((1u << lane) - 1u));
        g_pos4[m * MOLSIZE + a] = make_float4(x, y, z, __int_as_float(sp | (lrank << 8)));
    }

    // ---- triangle word-task sweep (10 tasks over 8 warps) ----
    {
        auto sweep = [&](int g, int w) {
            const int ar = g * 32 + lane;
            const float4 me = sc[ar];
            const int j0 = w * 32;
            unsigned msk = 0u;
            #pragma unroll
            for (int jj = 0; jj < 32; jj++) {
                const float4 pj = sc[j0 + jj];          // warp-uniform: broadcast
                const float dx = pj.x - me.x, dy = pj.y - me.y, dz = pj.z - me.z;
                const float d2 = __fmaf_rn(dx, dx, __fmaf_rn(dy, dy, dz * dz));
                msk |= (d2 < d2_thresh() ? 1u : 0u) << jj;
            }
            rmask[ar][w] = msk;
        };
        // primary tasks per warp: g digits 0,0,0,0,1,1,1,2 ; w digits 0,1,2,3,1,2,3,2
        sweep((int)((0x21110000u >> (wid * 4)) & 15u),
              (int)((0x23213210u >> (wid * 4)) & 15u));
        if (wid == 1) sweep(2, 3);      // extra task 9
        if (wid == 6) sweep(3, 3);      // extra task 10
    }
    __syncthreads();

    // ---- rows 0..127: post-mask, count, ordered scan ----
    unsigned r[4]; int excl = 0, cnt = 0;
    if (tid < 128) {
        const unsigned own = (nbw[a >> 5] >> (a & 31)) & 1u ? 0xffffffffu : 0u;
        #pragma unroll
        for (int w = 0; w < 4; w++) {
            r[w] = rmask[a][w] & gt_mask(a, w) & nbw[w] & own;
            cnt += __popc(r[w]);
        }
        int incl = cnt;
        #pragma unroll
        for (int o = 1; o < 32; o <<= 1) {
            int v = __shfl_up_sync(0xffffffffu, incl, o);
            if (lane >= o) incl += v;
        }
        if (lane == 31) sWC[wid] = incl;
        excl = incl - cnt;
    }
    __syncthreads();

    // ticket fires before the emit loop: the grid scan needs only the counts
    if (tid == 0) {
        g_pairCnt[m] = sWC[0] + sWC[1] + sWC[2] + sWC[3];
        __threadfence();
        const int old = atomicAdd(&g_ticket, 1);
        sLast = (old == (int)gridDim.x - 1);
    }

    if (tid < 128 && cnt) {
        int wb = 0;
        #pragma unroll
        for (int w = 0; w < 4; w++) if (w < wid) wb += sWC[w];
        excl += wb;
        unsigned short* dst = g_pairList + m * MAXP + excl;
        int k = 0;
        #pragma unroll
        for (int w = 0; w < 4; w++) {
            unsigned mm = r[w];
            while (mm) {
                int b = (w << 5) + __ffs((int)mm) - 1;
                mm &= mm - 1u;
                dst[k++] = (unsigned short)((a << 8) | b);
            }
        }
    }
    __syncthreads();

    // ---- last block: scan all 1024 counts ----
    if (sLast) {
        __threadfence();
        const int b4 = tid * 4;
        int oA[4], oB[4], sA = 0, sB = 0;
        #pragma unroll
        for (int q = 0; q < 4; q++) {
            oA[q] = g_atomCnt[b4 + q]; sA += oA[q];
            oB[q] = g_pairCnt[b4 + q]; sB += oB[q];
        }
        int ia = sA, ib = sB;
        #pragma unroll
        for (int o = 1; o < 32; o <<= 1) {
            int va = __shfl_up_sync(0xffffffffu, ia, o);
            int vb = __shfl_up_sync(0xffffffffu, ib, o);
            if (lane >= o) { ia += va; ib += vb; }
        }
        if (lane == 31) { sScanA[wid] = ia; sScanB[wid] = ib; }
        __syncthreads();
        int bA = 0, bB = 0;
        #pragma unroll
        for (int w = 0; w < 8; w++) if (w < wid) { bA += sScanA[w]; bB += sScanB[w]; }
        int pA = bA + ia - sA, pB = bB + ib - sB;
        #pragma unroll
        for (int q = 0; q < 4; q++) {
            g_atomBase[b4 + q] = pA; pA += oA[q];
            g_pairBase[b4 + q] = pB; pB += oB[q];
        }
        if (tid == 255) { g_nReal = pA; g_nPairs = pB; }
        if (tid == 0)   g_ticket = 0;    // reset for next graph replay
    }
}

// ============================================================================
// K2: scatter outputs; one molecule per 256-thread block. Single-LDG.128
// preamble via g_pos4; rsqrt-based pair math.
// ============================================================================
__global__ void __launch_bounds__(256)
k_write(float* __restrict__ out)
{
    __shared__ float4 sc[MOLSIZE];
    __shared__ short  ssp[MOLSIZE];
    __shared__ int    srank[MOLSIZE];

    const int tid = threadIdx.x;
    const int m   = blockIdx.x;

    const int nReal = g_nReal;
    const int nP    = g_nPairs;
    const int P0    = 3074 + 3 * nReal;

    const int base = g_pairBase[m];
    const int cnt  = g_pairCnt[m];
    const unsigned short* pl = g_pairList + m * MAXP;
    const int ab0  = pl[tid];            // prefetch first pair (always in-bounds)

    if (tid < MOLSIZE) {
        const float4 p  = g_pos4[m * MOLSIZE + tid];
        const int info  = __float_as_int(p.w);
        const int sp    = info & 255;
        const int rank  = g_atomBase[m] + (info >> 8);
        sc[tid]    = p;
        ssp[tid]   = (short)sp;
        srank[tid] = rank;
        if (sp > 0) {
            out[3074 + rank]             = (float)sp;                                            // Z
            out[3074 + nReal + rank]     = (float)(tid * (MOLSIZE + 1) + m * MOLSIZE * MOLSIZE); // maskd
            out[3074 + 2 * nReal + rank] = (float)m;                                             // atom_molid
        }
    }
    __syncthreads();

    const float molf  = (float)m;
    const float mbase = (float)(m * (MOLSIZE * MOLSIZE));

    for (int t = tid; t < cnt; t += 256) {
        const int ab = (t == tid) ? ab0 : pl[t];
        const int a2 = ab >> 8, b2 = ab & 255;
        const float4 pa = sc[a2], pb = sc[b2];
        const float dx = pb.x - pa.x, dy = pb.y - pa.y, dz = pb.z - pa.z;
        const float d2   = dx * dx + dy * dy + dz * dz;
        const float inv  = rsqrtf(d2);
        const float dist = d2 * inv;
        const int q = base + t;
        out[P0 + q]            = mbase + (float)(a2 * MOLSIZE + b2);  // mask
        out[P0 + nP + q]       = molf;                                // pair_molid
        out[P0 + 2 * nP + q]   = (float)ssp[a2];                      // ni
        out[P0 + 3 * nP + q]   = (float)ssp[b2];                      // nj
        out[P0 + 4 * nP + q]   = (float)srank[a2];                    // idxi
        out[P0 + 5 * nP + q]   = (float)srank[b2];                    // idxj
        out[P0 + 6 * nP + 3 * q + 0] = dx * inv;                      // xij
        out[P0 + 6 * nP + 3 * q + 1] = dy * inv;
        out[P0 + 6 * nP + 3 * q + 2] = dz * inv;
        out[P0 + 9 * nP + q]   = dist * 1.8897261258369282f;          // rij
    }
}

// ============================================================================
extern "C" void kernel_launch(void* const* d_in, const int* in_sizes, int n_in,
                              void* d_out, int out_size)
{
    const int*   species = (const int*)d_in[0];
    const float* coords  = (const float*)d_in[1];
    const float* tore    = (const float*)d_in[2];
    float*       out     = (float*)d_out;
    (void)in_sizes; (void)n_in; (void)out_size;

    k_count<<<NMOL, 256>>>(species, coords, tore, out);
    k_write<<<NMOL, 256>>>(out);
}